// round 2
// baseline (speedup 1.0000x reference)
#include <cuda_runtime.h>

#define NIN     64
#define NOUT    64
#define NJ      (NIN * NOUT)       // 4096
#define NKNOTS  10
#define NBASIS  6
#define BATCH_TILE 16
#define THREADS 512

// scratch accumulator for sum_b |spl[b, j]|  (device global: no allocations allowed)
__device__ float g_splacc[NJ];

__global__ void zero_acc_kernel() {
    int j = blockIdx.x * blockDim.x + threadIdx.x;
    if (j < NJ) g_splacc[j] = 0.0f;
}

__global__ __launch_bounds__(THREADS, 1)
void kan_main_kernel(const float* __restrict__ x,
                     const float* __restrict__ c_basis,
                     const float* __restrict__ c_spl,
                     const float* __restrict__ c_res,
                     const float* __restrict__ grid,
                     float* __restrict__ y_out,
                     int batch)
{
    // features: [c][b_local][i], c = 0..5 basis, 6 = silu
    __shared__ __align__(16) float sfeat[7][BATCH_TILE][NIN];
    __shared__ float sy[BATCH_TILE][NOUT];

    const int t    = threadIdx.x;
    const int lane = t & 31;     // i-pair index: i = 2*lane + ii
    const int oq   = t >> 5;     // o quad: o = oq*4 + q, q = 0..3
    const int b0   = blockIdx.x * BATCH_TILE;

    // ---- register-resident coefficients for this thread's 8 j-values ----
    float cb[4][2][NBASIS];
    float csp[4][2], crs[4][2];
    #pragma unroll
    for (int q = 0; q < 4; q++) {
        #pragma unroll
        for (int ii = 0; ii < 2; ii++) {
            int j = (oq * 4 + q) * NIN + lane * 2 + ii;
            #pragma unroll
            for (int c = 0; c < NBASIS; c++) cb[q][ii][c] = c_basis[j * NBASIS + c];
            csp[q][ii] = c_spl[j];
            crs[q][ii] = c_res[j];
        }
    }

    // ---- phase 1: spline basis + silu for BATCH_TILE x NIN x-values ----
    for (int p = t; p < BATCH_TILE * NIN; p += THREADS) {
        int bl = p >> 6;          // local batch
        int i  = p & 63;          // input index
        int b  = b0 + bl;
        float xv = (b < batch) ? x[b * NIN + i] : 0.0f;

        float kn[NKNOTS];
        #pragma unroll
        for (int m = 0; m < NKNOTS; m++) kn[m] = grid[i * NKNOTS + m];

        float bs[9];
        #pragma unroll
        for (int m = 0; m < 9; m++)
            bs[m] = (xv >= kn[m] && xv < kn[m + 1]) ? 1.0f : 0.0f;

        #pragma unroll
        for (int K = 1; K <= 3; K++) {
            #pragma unroll
            for (int m = 0; m <= 8 - K; m++) {
                float left  = (xv - kn[m]) / (kn[m + K] - kn[m]);
                float right = (kn[m + K + 1] - xv) / (kn[m + K + 1] - kn[m + 1]);
                bs[m] = left * bs[m] + right * bs[m + 1];
            }
        }
        #pragma unroll
        for (int c = 0; c < NBASIS; c++) sfeat[c][bl][i] = bs[c];
        float sig = 1.0f / (1.0f + __expf(-xv));
        sfeat[6][bl][i] = xv * sig;
    }
    __syncthreads();

    // ---- phase 2: fused spl / y / |spl| accumulation ----
    float acc[4][2];
    #pragma unroll
    for (int q = 0; q < 4; q++) { acc[q][0] = 0.0f; acc[q][1] = 0.0f; }

    #pragma unroll 1
    for (int bl = 0; bl < BATCH_TILE; bl++) {
        if (b0 + bl >= batch) break;

        float2 f[7];
        #pragma unroll
        for (int c = 0; c < 7; c++)
            f[c] = *(const float2*)&sfeat[c][bl][lane * 2];

        float yp[4];
        #pragma unroll
        for (int q = 0; q < 4; q++) {
            float s0 = cb[q][0][0] * f[0].x;
            float s1 = cb[q][1][0] * f[0].y;
            #pragma unroll
            for (int c = 1; c < NBASIS; c++) {
                s0 += cb[q][0][c] * f[c].x;
                s1 += cb[q][1][c] * f[c].y;
            }
            acc[q][0] += fabsf(s0);
            acc[q][1] += fabsf(s1);
            yp[q] = csp[q][0] * s0 + crs[q][0] * f[6].x
                  + csp[q][1] * s1 + crs[q][1] * f[6].y;
        }

        // reduce over the 32 lanes (= all 64 i) for 4 o's at once
        #pragma unroll
        for (int d = 16; d > 0; d >>= 1) {
            #pragma unroll
            for (int q = 0; q < 4; q++)
                yp[q] += __shfl_xor_sync(0xffffffffu, yp[q], d);
        }
        if (lane < 4) {
            float v = (lane == 0) ? yp[0] : (lane == 1) ? yp[1] : (lane == 2) ? yp[2] : yp[3];
            sy[bl][oq * 4 + lane] = v;
        }
    }
    __syncthreads();

    // ---- write y (coalesced) ----
    for (int p = t; p < BATCH_TILE * NOUT; p += THREADS) {
        int bl = p >> 6;
        int o  = p & 63;
        if (b0 + bl < batch)
            y_out[(b0 + bl) * NOUT + o] = sy[bl][o] * (1.0f / NIN);
    }

    // ---- accumulate |spl| partials ----
    #pragma unroll
    for (int q = 0; q < 4; q++) {
        #pragma unroll
        for (int ii = 0; ii < 2; ii++) {
            int j = (oq * 4 + q) * NIN + lane * 2 + ii;
            atomicAdd(&g_splacc[j], acc[q][ii]);
        }
    }
}

__global__ void finalize_kernel(const float* __restrict__ grid,
                                float* __restrict__ reg_out,
                                float inv_batch)
{
    int j = blockIdx.x * blockDim.x + threadIdx.x;
    if (j < NJ) {
        float norm = grid[j * NKNOTS + NKNOTS - 1] - grid[j * NKNOTS] + 1e-5f;
        reg_out[j] = g_splacc[j] * inv_batch / norm;
    }
}

extern "C" void kernel_launch(void* const* d_in, const int* in_sizes, int n_in,
                              void* d_out, int out_size)
{
    const float* x       = (const float*)d_in[0];
    const float* c_basis = (const float*)d_in[1];
    const float* c_spl   = (const float*)d_in[2];
    const float* c_res   = (const float*)d_in[3];
    const float* grid    = (const float*)d_in[4];

    int batch = in_sizes[0] / NIN;

    float* y_out   = (float*)d_out;              // (batch, 64)
    float* reg_out = y_out + (size_t)batch * NOUT; // (64, 64)

    zero_acc_kernel<<<(NJ + 255) / 256, 256>>>();

    int blocks = (batch + BATCH_TILE - 1) / BATCH_TILE;
    kan_main_kernel<<<blocks, THREADS>>>(x, c_basis, c_spl, c_res, grid, y_out, batch);

    finalize_kernel<<<(NJ + 255) / 256, 256>>>(grid, reg_out, 1.0f / (float)batch);
}